// round 7
// baseline (speedup 1.0000x reference)
#include <cuda_runtime.h>
#include <cuda_fp16.h>
#include <math.h>
#include <stdint.h>

// Problem dims (fixed by the dataset)
#define BSZ 4
#define LSZ 2048
#define DSZ 512
#define MROWS (BSZ * LSZ)   // 8192

// Scan chunking
#define NC 64               // chunks along L
#define LC (LSZ / NC)       // 32 steps per chunk

// GEMM tiling
#define BM 128
#define BN 128
#define BK 32
#define NCHUNK (DSZ / BK)   // 16

// smem: row = 32 halves (64B) padded to 80B -> conflict-free ldmatrix
#define ROWB 80
#define MATB (BM * ROWB)                 // 10KB per matrix
#define STAGEB (4 * MATB)                // Ahi|Alo|Whi|Wlo = 40KB
#define GEMM_SMEM (2 * STAGEB)           // double buffered: 80KB

#define SCAN_SMEM (LC * DSZ * 4)         // 64KB h tile for fused LN

// ---------------------------------------------------------------------------
// Scratch (static device globals; no runtime allocation allowed)
// ---------------------------------------------------------------------------
__device__ float    g_angle[MROWS * DSZ];
__device__ uint32_t g_xh[MROWS * DSZ / 2];   // half2-packed hi of x
__device__ uint32_t g_xl[MROWS * DSZ / 2];   // half2-packed lo of x
__device__ uint32_t g_wh[DSZ * DSZ / 2];
__device__ uint32_t g_wl[DSZ * DSZ / 2];
__device__ float2   g_P[BSZ * NC * DSZ];
__device__ float2   g_E[BSZ * NC * DSZ];

// ---------------------------------------------------------------------------
// helpers (baseline sm_80+ PTX only; harness compiles via compute_100)
// ---------------------------------------------------------------------------
__device__ __forceinline__ uint32_t smem_u32(const void* p) {
    uint32_t a;
    asm("{ .reg .u64 t; cvta.to.shared.u64 t, %1; cvt.u32.u64 %0, t; }" : "=r"(a) : "l"(p));
    return a;
}

__device__ __forceinline__ void split2(float x, float y, uint32_t& hi, uint32_t& lo) {
    __half2 h = __floats2half2_rn(x, y);
    float2 hf = __half22float2(h);
    __half2 l = __floats2half2_rn(x - hf.x, y - hf.y);
    hi = *reinterpret_cast<uint32_t*>(&h);
    lo = *reinterpret_cast<uint32_t*>(&l);
}

__device__ __forceinline__ void mma16(float* d, const uint32_t* a,
                                      uint32_t b0, uint32_t b1) {
    asm volatile(
        "mma.sync.aligned.m16n8k16.row.col.f32.f16.f16.f32 "
        "{%0,%1,%2,%3}, {%4,%5,%6,%7}, {%8,%9}, {%0,%1,%2,%3};"
        : "+f"(d[0]), "+f"(d[1]), "+f"(d[2]), "+f"(d[3])
        : "r"(a[0]), "r"(a[1]), "r"(a[2]), "r"(a[3]), "r"(b0), "r"(b1));
}

__device__ __forceinline__ void ldm4(uint32_t* r, uint32_t addr) {
    asm volatile("ldmatrix.sync.aligned.m8n8.x4.shared.b16 {%0,%1,%2,%3}, [%4];"
        : "=r"(r[0]), "=r"(r[1]), "=r"(r[2]), "=r"(r[3]) : "r"(addr));
}

#define CPA16(dst, src) \
    asm volatile("cp.async.cg.shared.global [%0], [%1], 16;" :: "r"(dst), "l"(src))
#define CPA_COMMIT() asm volatile("cp.async.commit_group;" ::: "memory")

// ---------------------------------------------------------------------------
// Kernel 0: split x and W into packed half2 hi/lo arrays
// ---------------------------------------------------------------------------
#define NX8 (MROWS * DSZ / 8)
#define NW8 (DSZ * DSZ / 8)

__global__ __launch_bounds__(256) void split_kernel(
    const float* __restrict__ x, const float* __restrict__ w)
{
    const int i = blockIdx.x * blockDim.x + threadIdx.x;
    if (i < NX8) {
        const float4* p = (const float4*)x + (size_t)i * 2;
        float4 v0 = p[0], v1 = p[1];
        uint4 H, L;
        split2(v0.x, v0.y, H.x, L.x);
        split2(v0.z, v0.w, H.y, L.y);
        split2(v1.x, v1.y, H.z, L.z);
        split2(v1.z, v1.w, H.w, L.w);
        ((uint4*)g_xh)[i] = H;
        ((uint4*)g_xl)[i] = L;
    } else if (i < NX8 + NW8) {
        const int j = i - NX8;
        const float4* p = (const float4*)w + (size_t)j * 2;
        float4 v0 = p[0], v1 = p[1];
        uint4 H, L;
        split2(v0.x, v0.y, H.x, L.x);
        split2(v0.z, v0.w, H.y, L.y);
        split2(v1.x, v1.y, H.z, L.z);
        split2(v1.z, v1.w, H.w, L.w);
        ((uint4*)g_wh)[j] = H;
        ((uint4*)g_wl)[j] = L;
    }
}

// ---------------------------------------------------------------------------
// GEMM: angle = x @ W^T + b, split-fp16 (hi*hi + hi*lo + lo*hi), mma.sync.
// cp.async staging of pre-split halves; 2 CTAs/SM target (<=128 regs).
// ---------------------------------------------------------------------------
__global__ __launch_bounds__(256, 2) void gemm_mma(const float* __restrict__ bias)
{
    extern __shared__ char dynsm[];
    const uint32_t sb = smem_u32(dynsm);

    const int tid  = threadIdx.x;
    const int wid  = tid >> 5;
    const int lane = tid & 31;
    const int g    = lane >> 2;
    const int tg   = lane & 3;
    const int bm   = blockIdx.y * BM;
    const int bn   = blockIdx.x * BN;
    const int m0w  = (wid >> 1) * 32;
    const int n0w  = (wid & 1) * 64;

    // ldmatrix addressing: lane -> (row = lane&15, k-half = lane>>4)
    const int lmr = lane & 15;
    const int lmk = (lane >> 4) * 16;   // bytes
    uint32_t aHi[2], bHi[4];
#pragma unroll
    for (int mt = 0; mt < 2; mt++)
        aHi[mt] = sb + (m0w + mt * 16 + lmr) * ROWB + lmk;
#pragma unroll
    for (int p = 0; p < 4; p++)
        bHi[p] = sb + 2 * MATB + (n0w + p * 16 + lmr) * ROWB + lmk;

    // cp.async staging: 512 16B-segments per matrix-pair half; thread does
    // 2 segs per matrix (tid + k*256), row = s>>2, seg = s&3.
    const char* xh = (const char*)g_xh;
    const char* xl = (const char*)g_xl;
    const char* wh = (const char*)g_wh;
    const char* wl = (const char*)g_wl;

    auto load_chunk = [&](int c, int buf) {
        const uint32_t st = sb + buf * STAGEB;
        const int kb = c * BK * 2;   // byte offset along K (half = 2B)
#pragma unroll
        for (int k = 0; k < 2; k++) {
            const int s   = tid + k * 256;
            const int row = s >> 2, seg = (s & 3) * 16;
            const uint32_t dst = st + row * ROWB + seg;
            const size_t  asrc = (size_t)(bm + row) * DSZ * 2 + kb + seg;
            const size_t  wsrc = (size_t)(bn + row) * DSZ * 2 + kb + seg;
            CPA16(dst,            xh + asrc);
            CPA16(dst + MATB,     xl + asrc);
            CPA16(dst + 2 * MATB, wh + wsrc);
            CPA16(dst + 3 * MATB, wl + wsrc);
        }
        CPA_COMMIT();
    };

    float C[2][8][4];
#pragma unroll
    for (int mt = 0; mt < 2; mt++)
#pragma unroll
        for (int nt = 0; nt < 8; nt++)
#pragma unroll
            for (int j = 0; j < 4; j++) C[mt][nt][j] = 0.f;

    load_chunk(0, 0);
    load_chunk(1, 1);

    for (int c = 0; c < NCHUNK; c++) {
        const int buf = c & 1;
        if (c < NCHUNK - 1) asm volatile("cp.async.wait_group 1;" ::: "memory");
        else                asm volatile("cp.async.wait_group 0;" ::: "memory");
        __syncthreads();

        const uint32_t boff = buf * STAGEB;
#pragma unroll
        for (int ks = 0; ks < 2; ks++) {
            const uint32_t off = boff + ks * 32;
            uint32_t ah[2][4], al[2][4];
#pragma unroll
            for (int mt = 0; mt < 2; mt++) {
                ldm4(ah[mt], aHi[mt] + off);
                ldm4(al[mt], aHi[mt] + MATB + off);
            }
#pragma unroll
            for (int p = 0; p < 4; p++) {
                uint32_t bh[4], bl[4];
                ldm4(bh, bHi[p] + off);
                ldm4(bl, bHi[p] + MATB + off);
#pragma unroll
                for (int mt = 0; mt < 2; mt++) {
                    mma16(C[mt][2 * p],     ah[mt], bh[0], bh[2]);
                    mma16(C[mt][2 * p],     ah[mt], bl[0], bl[2]);
                    mma16(C[mt][2 * p],     al[mt], bh[0], bh[2]);
                    mma16(C[mt][2 * p + 1], ah[mt], bh[1], bh[3]);
                    mma16(C[mt][2 * p + 1], ah[mt], bl[1], bl[3]);
                    mma16(C[mt][2 * p + 1], al[mt], bh[1], bh[3]);
                }
            }
        }
        __syncthreads();   // all warps done reading buf
        if (c + 2 < NCHUNK) load_chunk(c + 2, buf);
    }

    // epilogue: C + bias -> g_angle (float2 stores)
#pragma unroll
    for (int nt = 0; nt < 8; nt++) {
        const int col = bn + n0w + nt * 8 + 2 * tg;
        const float bz0 = bias[col], bz1 = bias[col + 1];
#pragma unroll
        for (int mt = 0; mt < 2; mt++) {
            const int row = bm + m0w + mt * 16 + g;
            float2 v0 = make_float2(C[mt][nt][0] + bz0, C[mt][nt][1] + bz1);
            float2 v1 = make_float2(C[mt][nt][2] + bz0, C[mt][nt][3] + bz1);
            *(float2*)(g_angle + (size_t)row * DSZ + col) = v0;
            *(float2*)(g_angle + (size_t)(row + 8) * DSZ + col) = v1;
        }
    }
}

// ---------------------------------------------------------------------------
// Complex linear scan:  g[t] = c[t]*g[t-1] + x[t]
// ---------------------------------------------------------------------------
#define EDECAY 0.999000499833375f   // expf(-0.001f)

__global__ __launch_bounds__(512) void scan_phase1(
    const float* __restrict__ x, const float* __restrict__ scale,
    const float* __restrict__ lre, const float* __restrict__ lim)
{
    const int b = blockIdx.x / NC;
    const int c = blockIdx.x % NC;
    const int d = threadIdx.x;

    const float sc = scale[d];
    const size_t base = ((size_t)b * LSZ + (size_t)c * LC) * DSZ + d;
    const float* ap = g_angle + base;
    const float* xp = x + base;

    float gr = 0.f, gi = 0.f, Pr = 1.f, Pi = 0.f;
    int tt = 0;
    if (c == 0) {
        float a0 = ap[0], x0 = xp[0];
        float s0, c0;
        __sincosf(a0 * sc, &s0, &c0);
        const float lr_ = lre[d], li_ = lim[d];
        gr = x0 + EDECAY * (c0 * lr_ - s0 * li_);
        gi = EDECAY * (c0 * li_ + s0 * lr_);
        tt = 1;
    }
    for (; tt < LC; tt++) {
        float a  = ap[(size_t)tt * DSZ];
        float xv = xp[(size_t)tt * DSZ];
        float s, co;
        __sincosf(a * sc, &s, &co);
        const float cr = EDECAY * co, ci = EDECAY * s;
        float ngr = fmaf(cr, gr, fmaf(-ci, gi, xv));
        float ngi = fmaf(cr, gi, ci * gr);
        gr = ngr; gi = ngi;
        float nPr = fmaf(cr, Pr, -ci * Pi);
        float nPi = fmaf(cr, Pi,  ci * Pr);
        Pr = nPr; Pi = nPi;
    }
    const int idx = (b * NC + c) * DSZ + d;
    g_E[idx] = make_float2(gr, gi);
    g_P[idx] = make_float2(Pr, Pi);
}

// Phase 2: barrier-free scan into smem h[LC][DSZ], then per-warp LN rows.
__global__ __launch_bounds__(512) void scan_phase2_ln(
    const float* __restrict__ x, const float* __restrict__ scale,
    const float* __restrict__ lre, const float* __restrict__ lim,
    const float* __restrict__ gamma, const float* __restrict__ beta,
    float* __restrict__ y)
{
    extern __shared__ char dynsm[];
    float* hsm = (float*)dynsm;   // [LC][DSZ]

    const int b = blockIdx.x / NC;
    const int c = blockIdx.x % NC;
    const int d = threadIdx.x;
    const int lane = d & 31, w = d >> 5;

    const float sc = scale[d];

    float gr = 0.f, gi = 0.f;
    for (int j = 0; j < c; j++) {
        const int idx = (b * NC + j) * DSZ + d;
        const float2 P = g_P[idx];
        const float2 E = g_E[idx];
        float ngr = fmaf(P.x, gr, fmaf(-P.y, gi, E.x));
        float ngi = fmaf(P.x, gi, fmaf( P.y, gr, E.y));
        gr = ngr; gi = ngi;
    }

    const size_t base = ((size_t)b * LSZ + (size_t)c * LC) * DSZ + d;
    const float* ap = g_angle + base;
    const float* xp = x + base;

    int tt = 0;
    if (c == 0) {
        float a0 = ap[0], x0 = xp[0];
        float s0, c0;
        __sincosf(a0 * sc, &s0, &c0);
        const float lr_ = lre[d], li_ = lim[d];
        gr = x0 + EDECAY * (c0 * lr_ - s0 * li_);
        gi = EDECAY * (c0 * li_ + s0 * lr_);
        hsm[d] = gr;
        tt = 1;
    }
    for (; tt < LC; tt++) {
        float a  = ap[(size_t)tt * DSZ];
        float xv = xp[(size_t)tt * DSZ];
        float s, co;
        __sincosf(a * sc, &s, &co);
        const float cr = EDECAY * co, ci = EDECAY * s;
        float ngr = fmaf(cr, gr, fmaf(-ci, gi, xv));
        float ngi = fmaf(cr, gi, ci * gr);
        gr = ngr; gi = ngi;
        hsm[tt * DSZ + d] = gr;
    }
    __syncthreads();

    float4 g4[4], b4[4];
#pragma unroll
    for (int j = 0; j < 4; j++) {
        g4[j] = ((const float4*)gamma)[lane + j * 32];
        b4[j] = ((const float4*)beta)[lane + j * 32];
    }
    float* yrowbase = y + ((size_t)b * LSZ + (size_t)c * LC) * DSZ;

#pragma unroll
    for (int rr = w; rr < LC; rr += 16) {
        const float4* hp = (const float4*)(hsm + rr * DSZ);
        float4 v[4];
        float s = 0.f, ss = 0.f;
#pragma unroll
        for (int j = 0; j < 4; j++) {
            v[j] = hp[lane + j * 32];
            s  += v[j].x + v[j].y + v[j].z + v[j].w;
            ss += v[j].x * v[j].x + v[j].y * v[j].y
                + v[j].z * v[j].z + v[j].w * v[j].w;
        }
#pragma unroll
        for (int o = 16; o > 0; o >>= 1) {
            s  += __shfl_xor_sync(0xffffffffu, s,  o);
            ss += __shfl_xor_sync(0xffffffffu, ss, o);
        }
        const float mu   = s * (1.0f / DSZ);
        const float var  = ss * (1.0f / DSZ) - mu * mu;
        const float rstd = rsqrtf(var + 1e-5f);

        float4* yp = (float4*)(yrowbase + (size_t)rr * DSZ);
#pragma unroll
        for (int j = 0; j < 4; j++) {
            float4 o;
            o.x = (v[j].x - mu) * rstd * g4[j].x + b4[j].x;
            o.y = (v[j].y - mu) * rstd * g4[j].y + b4[j].y;
            o.z = (v[j].z - mu) * rstd * g4[j].z + b4[j].z;
            o.w = (v[j].w - mu) * rstd * g4[j].w + b4[j].w;
            yp[lane + j * 32] = o;
        }
    }
}

// ---------------------------------------------------------------------------
// Launch
// ---------------------------------------------------------------------------
extern "C" void kernel_launch(void* const* d_in, const int* in_sizes, int n_in,
                              void* d_out, int out_size)
{
    const float* x     = (const float*)d_in[0];
    const float* fc_w  = (const float*)d_in[1];
    const float* fc_b  = (const float*)d_in[2];
    const float* scale = (const float*)d_in[3];
    const float* lre   = (const float*)d_in[4];
    const float* lim   = (const float*)d_in[5];
    const float* gamma = (const float*)d_in[6];
    const float* beta  = (const float*)d_in[7];
    float* y = (float*)d_out;

    cudaFuncSetAttribute(gemm_mma, cudaFuncAttributeMaxDynamicSharedMemorySize,
                         GEMM_SMEM);
    cudaFuncSetAttribute(scan_phase2_ln, cudaFuncAttributeMaxDynamicSharedMemorySize,
                         SCAN_SMEM);

    const int nsplit = (NX8 + NW8 + 255) / 256;
    split_kernel<<<nsplit, 256>>>(x, fc_w);

    dim3 ggrid(DSZ / BN, MROWS / BM);   // (4, 64) = 256 CTAs
    gemm_mma<<<ggrid, 256, GEMM_SMEM>>>(fc_b);

    scan_phase1<<<BSZ * NC, DSZ>>>(x, scale, lre, lim);
    scan_phase2_ln<<<BSZ * NC, DSZ, SCAN_SMEM>>>(x, scale, lre, lim, gamma, beta, y);
}